// round 1
// baseline (speedup 1.0000x reference)
#include <cuda_runtime.h>
#include <cstdint>

#define LSEQ 2048
#define DKH  64
#define BQ   64
#define BK   64
#define PAD  68   // row stride in floats (16B-aligned: 272B)

// Small fallback scratch in case output turns out to be attn-only.
__device__ float g_ctx_scratch[2 * 16 * 2048 * 64];

__global__ void __launch_bounds__(256, 2)
relattn_kernel(const float* __restrict__ Q, const float* __restrict__ K,
               const float* __restrict__ V, const float* __restrict__ Er,
               float* __restrict__ ctx, float* __restrict__ attn)
{
    extern __shared__ float sm[];
    float* Qs   = sm;                  // [64][PAD]  (phase B: Ps)
    float* Ks   = Qs + BQ * PAD;       // [64][PAD]  (phase B: Vs)
    float* Ers  = Ks + BK * PAD;       // [128][PAD]
    float* rowm = Ers + 128 * PAD;     // [64]
    float* rowz = rowm + 64;           // [64]

    if (ctx == nullptr) ctx = g_ctx_scratch;

    const int qt = (int)(gridDim.x - 1) - (int)blockIdx.x;  // heavy tiles first
    const int bh = blockIdx.y;
    const int q0 = qt * BQ;
    const int t  = threadIdx.x;
    const int tq = t >> 4;   // 0..15 -> q rows tq*4..tq*4+3
    const int tk = t & 15;   // 0..15 -> k cols tk*4..tk*4+3

    const float* Qg = Q + (size_t)bh * LSEQ * DKH;
    const float* Kg = K + (size_t)bh * LSEQ * DKH;
    const float* Vg = V + (size_t)bh * LSEQ * DKH;
    float* attng = attn + (size_t)bh * LSEQ * LSEQ;
    float* ctxg  = ctx  + (size_t)bh * LSEQ * DKH;

    // ---- load Q tile ----
    for (int i = t; i < BQ * DKH / 4; i += 256) {
        int r = i >> 4, c = i & 15;
        float4 v = ((const float4*)(Qg + (size_t)(q0 + r) * DKH))[c];
        ((float4*)(Qs + r * PAD))[c] = v;
    }
    __syncthreads();

    // Online softmax stats, replicated across the 16 lanes that share q rows.
    float m_run[4], z_run[4];
#pragma unroll
    for (int i = 0; i < 4; i++) { m_run[i] = -3.0e38f; z_run[i] = 0.f; }

    const int erbase = 4 * (tk - tq) + 60;  // rel index for (j-i) = -3

    // ================= Phase A: scores + raw store + online stats =========
    for (int kt = 0; kt <= qt; kt++) {
        const int k0 = kt * BK;
        // load K tile
        for (int i = t; i < BK * DKH / 4; i += 256) {
            int r = i >> 4, c = i & 15;
            ((float4*)(Ks + r * PAD))[c] =
                ((const float4*)(Kg + (size_t)(k0 + r) * DKH))[c];
        }
        // load Er rows: rel in [0,127], e = base + rel  (rel = (k-q)+63, with +1 headroom)
        const int base = k0 - q0 + LSEQ - 64;
        for (int i = t; i < 128 * DKH / 4; i += 256) {
            int rel = i >> 4, c = i & 15;
            int e = base + rel;
            float4 v = make_float4(0.f, 0.f, 0.f, 0.f);
            if (e >= 0 && e < LSEQ)
                v = ((const float4*)(Er + (size_t)e * DKH))[c];
            ((float4*)(Ers + rel * PAD))[c] = v;
        }
        __syncthreads();

        float acc[4][4];
#pragma unroll
        for (int i = 0; i < 4; i++)
#pragma unroll
            for (int j = 0; j < 4; j++) acc[i][j] = 0.f;

#pragma unroll
        for (int d4 = 0; d4 < 16; d4++) {
            float4 qf[4], kf[4], ef[7];
#pragma unroll
            for (int i = 0; i < 4; i++) qf[i] = ((float4*)(Qs + (tq * 4 + i) * PAD))[d4];
#pragma unroll
            for (int j = 0; j < 4; j++) kf[j] = ((float4*)(Ks + (tk * 4 + j) * PAD))[d4];
#pragma unroll
            for (int m = 0; m < 7; m++) ef[m] = ((float4*)(Ers + (erbase + m) * PAD))[d4];
#pragma unroll
            for (int i = 0; i < 4; i++) {
#pragma unroll
                for (int j = 0; j < 4; j++) {
                    const float4 e = ef[j - i + 3];
                    float s = acc[i][j];
                    s = fmaf(qf[i].x, kf[j].x, s);
                    s = fmaf(qf[i].y, kf[j].y, s);
                    s = fmaf(qf[i].z, kf[j].z, s);
                    s = fmaf(qf[i].w, kf[j].w, s);
                    s = fmaf(qf[i].x, e.x, s);
                    s = fmaf(qf[i].y, e.y, s);
                    s = fmaf(qf[i].z, e.z, s);
                    s = fmaf(qf[i].w, e.w, s);
                    acc[i][j] = s;
                }
            }
        }

        // scale, mask, row stats, raw store
        const int kg0 = k0 + tk * 4;
#pragma unroll
        for (int i = 0; i < 4; i++) {
            const int q = q0 + tq * 4 + i;
            float rm = -3.0e38f;
#pragma unroll
            for (int j = 0; j < 4; j++) {
                float s = acc[i][j] * 0.125f;
                if (kg0 + j > q) s = -1e9f;
                acc[i][j] = s;
                rm = fmaxf(rm, s);
            }
#pragma unroll
            for (int off = 8; off >= 1; off >>= 1)
                rm = fmaxf(rm, __shfl_xor_sync(0xffffffffu, rm, off));
            float rs = __expf(acc[i][0] - rm) + __expf(acc[i][1] - rm)
                     + __expf(acc[i][2] - rm) + __expf(acc[i][3] - rm);
#pragma unroll
            for (int off = 8; off >= 1; off >>= 1)
                rs += __shfl_xor_sync(0xffffffffu, rs, off);
            // merge into running stats (all 16 lanes redundantly)
            const float mo = m_run[i];
            const float mn = fmaxf(mo, rm);
            z_run[i] = z_run[i] * __expf(mo - mn) + rs * __expf(rm - mn);
            m_run[i] = mn;
            // raw score store
            float4 sv = make_float4(acc[i][0], acc[i][1], acc[i][2], acc[i][3]);
            *((float4*)(attng + (size_t)q * LSEQ + kg0)) = sv;
        }
        __syncthreads();
    }

    // publish stats (one owner lane per row group)
    if (tk == 0) {
#pragma unroll
        for (int i = 0; i < 4; i++) {
            rowm[tq * 4 + i] = m_run[i];
            rowz[tq * 4 + i] = 1.f / z_run[i];
        }
    }

    // ================= Phase B: normalize + PV =============================
    float* Ps = Qs;
    float* Vs = Ks;
    float cacc[4][4];
#pragma unroll
    for (int i = 0; i < 4; i++)
#pragma unroll
        for (int j = 0; j < 4; j++) cacc[i][j] = 0.f;

    for (int kt = 0; kt <= qt; kt++) {
        const int k0 = kt * BK;
        __syncthreads();  // protect Ps/Vs reuse (covers Qs reuse on first iter)
        // load V tile
        for (int i = t; i < BK * DKH / 4; i += 256) {
            int r = i >> 4, c = i & 15;
            ((float4*)(Vs + r * PAD))[c] =
                ((const float4*)(Vg + (size_t)(k0 + r) * DKH))[c];
        }
        // read raw S, normalize, stage in smem + final attn store
        for (int i = t; i < BQ * BK / 4; i += 256) {
            int r = i >> 4, c = i & 15;
            size_t gi = (size_t)(q0 + r) * LSEQ + k0 + c * 4;
            float4 s = *((const float4*)(attng + gi));
            const float m = rowm[r], iz = rowz[r];
            float4 p;
            p.x = __expf(s.x - m) * iz;
            p.y = __expf(s.y - m) * iz;
            p.z = __expf(s.z - m) * iz;
            p.w = __expf(s.w - m) * iz;
            ((float4*)(Ps + r * PAD))[c] = p;
            *((float4*)(attng + gi)) = p;
        }
        __syncthreads();

#pragma unroll 8
        for (int k = 0; k < BK; k++) {
            float4 vf = ((float4*)(Vs + k * PAD))[tk];
            float pf[4];
#pragma unroll
            for (int i = 0; i < 4; i++) pf[i] = Ps[(tq * 4 + i) * PAD + k];
#pragma unroll
            for (int i = 0; i < 4; i++) {
                cacc[i][0] = fmaf(pf[i], vf.x, cacc[i][0]);
                cacc[i][1] = fmaf(pf[i], vf.y, cacc[i][1]);
                cacc[i][2] = fmaf(pf[i], vf.z, cacc[i][2]);
                cacc[i][3] = fmaf(pf[i], vf.w, cacc[i][3]);
            }
        }
    }

    // zero-fill the never-touched future tiles (d_out is poisoned)
    const float4 z4 = make_float4(0.f, 0.f, 0.f, 0.f);
    for (int kt = qt + 1; kt < LSEQ / BK; kt++) {
        const int k0 = kt * BK;
        for (int i = t; i < BQ * BK / 4; i += 256) {
            int r = i >> 4, c = i & 15;
            ((float4*)(attng + (size_t)(q0 + r) * LSEQ + k0))[c] = z4;
        }
    }

    // write context
#pragma unroll
    for (int i = 0; i < 4; i++) {
        const int q = q0 + tq * 4 + i;
        float4 cv = make_float4(cacc[i][0], cacc[i][1], cacc[i][2], cacc[i][3]);
        *((float4*)(ctxg + (size_t)q * DKH + tk * 4)) = cv;
    }
}

extern "C" void kernel_launch(void* const* d_in, const int* in_sizes, int n_in,
                              void* d_out, int out_size) {
    const float* Q  = (const float*)d_in[0];
    const float* K  = (const float*)d_in[1];
    const float* V  = (const float*)d_in[2];
    // d_in[3] = attn_mask (bool) — causal, recomputed on the fly
    const float* Er = (const float*)d_in[4];

    const long long CTXN = (long long)2 * 16 * 2048 * 64;     // 4,194,304
    const long long ATTN = (long long)2 * 16 * 2048 * 2048;   // 134,217,728

    float* out = (float*)d_out;
    float* ctx;
    float* attn;
    if ((long long)out_size >= CTXN + ATTN) {        // concat(context, attn)
        ctx = out;
        attn = out + CTXN;
    } else if ((long long)out_size == ATTN) {        // attn only
        ctx = nullptr;                               // kernel falls back to scratch
        attn = out;
    } else {                                         // unexpected — best effort
        ctx = out;
        attn = out;
    }

    const int smem = (BQ * PAD + BK * PAD + 128 * PAD + 128) * (int)sizeof(float);
    cudaFuncSetAttribute(relattn_kernel,
                         cudaFuncAttributeMaxDynamicSharedMemorySize, smem);
    dim3 grid(LSEQ / BQ, 32);
    relattn_kernel<<<grid, 256, smem>>>(Q, K, V, Er, ctx, attn);
}

// round 2
// speedup vs baseline: 1.0032x; 1.0032x over previous
#include <cuda_runtime.h>
#include <cstdint>

#define LSEQ 2048
#define DKH  64
#define BQ   64
#define BK   64
#define PAD  68   // row stride in floats (16B-aligned: 272B)

// Small fallback scratch in case output turns out to be attn-only.
__device__ float g_ctx_scratch[2 * 16 * 2048 * 64];

__global__ void __launch_bounds__(256, 2)
relattn_kernel(const float* __restrict__ Q, const float* __restrict__ K,
               const float* __restrict__ V, const float* __restrict__ Er,
               float* __restrict__ ctx, float* __restrict__ attn)
{
    extern __shared__ float sm[];
    float* Qs   = sm;                  // [64][PAD]  (phase B: Ps)
    float* Ks   = Qs + BQ * PAD;       // [64][PAD]  (phase B: Vs)
    float* Ers  = Ks + BK * PAD;       // [128][PAD]
    float* rowm = Ers + 128 * PAD;     // [64]
    float* rowz = rowm + 64;           // [64]

    if (ctx == nullptr) ctx = g_ctx_scratch;

    const int qt = (int)(gridDim.x - 1) - (int)blockIdx.x;  // heavy tiles first
    const int bh = blockIdx.y;
    const int q0 = qt * BQ;
    const int t  = threadIdx.x;
    const int tq = t >> 4;   // 0..15 -> q rows tq*4..tq*4+3
    const int tk = t & 15;   // 0..15 -> k cols tk*4..tk*4+3

    const float* Qg = Q + (size_t)bh * LSEQ * DKH;
    const float* Kg = K + (size_t)bh * LSEQ * DKH;
    const float* Vg = V + (size_t)bh * LSEQ * DKH;
    float* attng = attn + (size_t)bh * LSEQ * LSEQ;
    float* ctxg  = ctx  + (size_t)bh * LSEQ * DKH;

    // ---- load Q tile ----
    for (int i = t; i < BQ * DKH / 4; i += 256) {
        int r = i >> 4, c = i & 15;
        float4 v = ((const float4*)(Qg + (size_t)(q0 + r) * DKH))[c];
        ((float4*)(Qs + r * PAD))[c] = v;
    }
    __syncthreads();

    // Online softmax stats, replicated across the 16 lanes that share q rows.
    float m_run[4], z_run[4];
#pragma unroll
    for (int i = 0; i < 4; i++) { m_run[i] = -3.0e38f; z_run[i] = 0.f; }

    const int erbase = 4 * (tk - tq) + 60;  // rel index for (j-i) = -3

    // ================= Phase A: scores + raw store + online stats =========
    for (int kt = 0; kt <= qt; kt++) {
        const int k0 = kt * BK;
        // load K tile
        for (int i = t; i < BK * DKH / 4; i += 256) {
            int r = i >> 4, c = i & 15;
            ((float4*)(Ks + r * PAD))[c] =
                ((const float4*)(Kg + (size_t)(k0 + r) * DKH))[c];
        }
        // load Er rows: rel in [0,127], e = base + rel  (rel = (k-q)+63, with +1 headroom)
        const int base = k0 - q0 + LSEQ - 64;
        for (int i = t; i < 128 * DKH / 4; i += 256) {
            int rel = i >> 4, c = i & 15;
            int e = base + rel;
            float4 v = make_float4(0.f, 0.f, 0.f, 0.f);
            if (e >= 0 && e < LSEQ)
                v = ((const float4*)(Er + (size_t)e * DKH))[c];
            ((float4*)(Ers + rel * PAD))[c] = v;
        }
        __syncthreads();

        float acc[4][4];
#pragma unroll
        for (int i = 0; i < 4; i++)
#pragma unroll
            for (int j = 0; j < 4; j++) acc[i][j] = 0.f;

#pragma unroll
        for (int d4 = 0; d4 < 16; d4++) {
            float4 qf[4], kf[4], ef[7];
#pragma unroll
            for (int i = 0; i < 4; i++) qf[i] = ((float4*)(Qs + (tq * 4 + i) * PAD))[d4];
#pragma unroll
            for (int j = 0; j < 4; j++) kf[j] = ((float4*)(Ks + (tk * 4 + j) * PAD))[d4];
#pragma unroll
            for (int m = 0; m < 7; m++) ef[m] = ((float4*)(Ers + (erbase + m) * PAD))[d4];
#pragma unroll
            for (int i = 0; i < 4; i++) {
#pragma unroll
                for (int j = 0; j < 4; j++) {
                    const float4 e = ef[j - i + 3];
                    float s = acc[i][j];
                    s = fmaf(qf[i].x, kf[j].x, s);
                    s = fmaf(qf[i].y, kf[j].y, s);
                    s = fmaf(qf[i].z, kf[j].z, s);
                    s = fmaf(qf[i].w, kf[j].w, s);
                    s = fmaf(qf[i].x, e.x, s);
                    s = fmaf(qf[i].y, e.y, s);
                    s = fmaf(qf[i].z, e.z, s);
                    s = fmaf(qf[i].w, e.w, s);
                    acc[i][j] = s;
                }
            }
        }

        // scale, mask, row stats, raw store
        const int kg0 = k0 + tk * 4;
#pragma unroll
        for (int i = 0; i < 4; i++) {
            const int q = q0 + tq * 4 + i;
            float rm = -3.0e38f;
#pragma unroll
            for (int j = 0; j < 4; j++) {
                float s = acc[i][j] * 0.125f;
                if (kg0 + j > q) s = -1e9f;
                acc[i][j] = s;
                rm = fmaxf(rm, s);
            }
#pragma unroll
            for (int off = 8; off >= 1; off >>= 1)
                rm = fmaxf(rm, __shfl_xor_sync(0xffffffffu, rm, off));
            float rs = __expf(acc[i][0] - rm) + __expf(acc[i][1] - rm)
                     + __expf(acc[i][2] - rm) + __expf(acc[i][3] - rm);
#pragma unroll
            for (int off = 8; off >= 1; off >>= 1)
                rs += __shfl_xor_sync(0xffffffffu, rs, off);
            // merge into running stats (all 16 lanes redundantly)
            const float mo = m_run[i];
            const float mn = fmaxf(mo, rm);
            z_run[i] = z_run[i] * __expf(mo - mn) + rs * __expf(rm - mn);
            m_run[i] = mn;
            // raw score store
            float4 sv = make_float4(acc[i][0], acc[i][1], acc[i][2], acc[i][3]);
            *((float4*)(attng + (size_t)q * LSEQ + kg0)) = sv;
        }
        __syncthreads();
    }

    // publish stats (one owner lane per row group)
    if (tk == 0) {
#pragma unroll
        for (int i = 0; i < 4; i++) {
            rowm[tq * 4 + i] = m_run[i];
            rowz[tq * 4 + i] = 1.f / z_run[i];
        }
    }

    // ================= Phase B: normalize + PV =============================
    float* Ps = Qs;
    float* Vs = Ks;
    float cacc[4][4];
#pragma unroll
    for (int i = 0; i < 4; i++)
#pragma unroll
        for (int j = 0; j < 4; j++) cacc[i][j] = 0.f;

    for (int kt = 0; kt <= qt; kt++) {
        const int k0 = kt * BK;
        __syncthreads();  // protect Ps/Vs reuse (covers Qs reuse on first iter)
        // load V tile
        for (int i = t; i < BK * DKH / 4; i += 256) {
            int r = i >> 4, c = i & 15;
            ((float4*)(Vs + r * PAD))[c] =
                ((const float4*)(Vg + (size_t)(k0 + r) * DKH))[c];
        }
        // read raw S, normalize, stage in smem + final attn store
        for (int i = t; i < BQ * BK / 4; i += 256) {
            int r = i >> 4, c = i & 15;
            size_t gi = (size_t)(q0 + r) * LSEQ + k0 + c * 4;
            float4 s = *((const float4*)(attng + gi));
            const float m = rowm[r], iz = rowz[r];
            float4 p;
            p.x = __expf(s.x - m) * iz;
            p.y = __expf(s.y - m) * iz;
            p.z = __expf(s.z - m) * iz;
            p.w = __expf(s.w - m) * iz;
            ((float4*)(Ps + r * PAD))[c] = p;
            *((float4*)(attng + gi)) = p;
        }
        __syncthreads();

#pragma unroll 8
        for (int k = 0; k < BK; k++) {
            float4 vf = ((float4*)(Vs + k * PAD))[tk];
            float pf[4];
#pragma unroll
            for (int i = 0; i < 4; i++) pf[i] = Ps[(tq * 4 + i) * PAD + k];
#pragma unroll
            for (int i = 0; i < 4; i++) {
                cacc[i][0] = fmaf(pf[i], vf.x, cacc[i][0]);
                cacc[i][1] = fmaf(pf[i], vf.y, cacc[i][1]);
                cacc[i][2] = fmaf(pf[i], vf.z, cacc[i][2]);
                cacc[i][3] = fmaf(pf[i], vf.w, cacc[i][3]);
            }
        }
    }

    // zero-fill the never-touched future tiles (d_out is poisoned)
    const float4 z4 = make_float4(0.f, 0.f, 0.f, 0.f);
    for (int kt = qt + 1; kt < LSEQ / BK; kt++) {
        const int k0 = kt * BK;
        for (int i = t; i < BQ * BK / 4; i += 256) {
            int r = i >> 4, c = i & 15;
            ((float4*)(attng + (size_t)(q0 + r) * LSEQ + k0))[c] = z4;
        }
    }

    // write context
#pragma unroll
    for (int i = 0; i < 4; i++) {
        const int q = q0 + tq * 4 + i;
        float4 cv = make_float4(cacc[i][0], cacc[i][1], cacc[i][2], cacc[i][3]);
        *((float4*)(ctxg + (size_t)q * DKH + tk * 4)) = cv;
    }
}

extern "C" void kernel_launch(void* const* d_in, const int* in_sizes, int n_in,
                              void* d_out, int out_size) {
    const float* Q  = (const float*)d_in[0];
    const float* K  = (const float*)d_in[1];
    const float* V  = (const float*)d_in[2];
    // d_in[3] = attn_mask (bool) — causal, recomputed on the fly
    const float* Er = (const float*)d_in[4];

    const long long CTXN = (long long)2 * 16 * 2048 * 64;     // 4,194,304
    const long long ATTN = (long long)2 * 16 * 2048 * 2048;   // 134,217,728

    float* out = (float*)d_out;
    float* ctx;
    float* attn;
    if ((long long)out_size >= CTXN + ATTN) {        // concat(context, attn)
        ctx = out;
        attn = out + CTXN;
    } else if ((long long)out_size == ATTN) {        // attn only
        ctx = nullptr;                               // kernel falls back to scratch
        attn = out;
    } else {                                         // unexpected — best effort
        ctx = out;
        attn = out;
    }

    const int smem = (BQ * PAD + BK * PAD + 128 * PAD + 128) * (int)sizeof(float);
    cudaFuncSetAttribute(relattn_kernel,
                         cudaFuncAttributeMaxDynamicSharedMemorySize, smem);
    dim3 grid(LSEQ / BQ, 32);
    relattn_kernel<<<grid, 256, smem>>>(Q, K, V, Er, ctx, attn);
}

// round 3
// speedup vs baseline: 2.0081x; 2.0016x over previous
#include <cuda_runtime.h>
#include <cstdint>

#define LSEQ 2048
#define D    64

// Transposed Q (m=0..31), K (m=32..63), Er (m=64): each [64][2048]
__device__ float g_T[65 * D * LSEQ];
__device__ float g_IZ[32 * LSEQ];
__device__ float g_ctx_scratch[2 * 16 * 2048 * 64];

typedef unsigned long long ull;

__device__ __forceinline__ int swz(int s) { return s ^ ((s >> 3) & 7); }
__device__ __forceinline__ ull pk2(float lo, float hi) {
    ull r; asm("mov.b64 %0, {%1, %2};" : "=l"(r) : "f"(lo), "f"(hi)); return r;
}
__device__ __forceinline__ void up2(ull v, float& lo, float& hi) {
    asm("mov.b64 {%0, %1}, %2;" : "=f"(lo), "=f"(hi) : "l"(v));
}
__device__ __forceinline__ void fma2(ull& a, ull x, ull y) {
    asm("fma.rn.f32x2 %0, %1, %2, %0;" : "+l"(a) : "l"(x), "l"(y));
}

// ---------------- transpose [2048][64] -> [64][2048] ----------------
__global__ void transpose_kernel(const float* __restrict__ Q,
                                 const float* __restrict__ K,
                                 const float* __restrict__ Er)
{
    __shared__ float sm[128 * 65];
    const int m  = blockIdx.x;
    const int r0 = blockIdx.y * 128;
    const float* src;
    if (m < 32)      src = Q  + (size_t)m        * LSEQ * D;
    else if (m < 64) src = K  + (size_t)(m - 32) * LSEQ * D;
    else             src = Er;
    float* dst = g_T + (size_t)m * D * LSEQ;
    const int t = threadIdx.x;
    for (int i = t; i < 128 * 16; i += 256) {
        int r = i >> 4, c = i & 15;
        float4 v = ((const float4*)(src + (size_t)(r0 + r) * D))[c];
        float* p = sm + r * 65 + 4 * c;
        p[0] = v.x; p[1] = v.y; p[2] = v.z; p[3] = v.w;
    }
    __syncthreads();
    for (int i = t; i < 64 * 32; i += 256) {
        int d = i >> 5, jj = i & 31;
        float4 v;
        v.x = sm[(4 * jj + 0) * 65 + d];
        v.y = sm[(4 * jj + 1) * 65 + d];
        v.z = sm[(4 * jj + 2) * 65 + d];
        v.w = sm[(4 * jj + 3) * 65 + d];
        ((float4*)(dst + (size_t)d * LSEQ + r0))[jj] = v;
    }
}

// ============ Kernel A: S = Q(K+Er)/8, exp, unnormalized store, 1/z ========
// block: 128 thr, q-tile 64, k-tile 128, 8q x 8k per thread.
__global__ void __launch_bounds__(128, 2)
score_kernel(float* __restrict__ attn)
{
    extern __shared__ float sm[];
    float* smQ = sm;                 // [64][64]
    float* smK = sm + 4096;          // [64][128]
    float* smE = sm + 12288;         // [64][192]

    const int qt = 31 - (int)blockIdx.x;
    const int bh = blockIdx.y;
    const int q0 = qt * 64;
    const int t  = threadIdx.x;
    const int tq = t >> 4;           // 0..7
    const int tk = t & 15;           // 0..15

    const float* QT = g_T + (size_t)bh * (D * LSEQ);
    const float* KT = g_T + (size_t)(32 + bh) * (D * LSEQ);
    const float* ET = g_T + (size_t)64 * (D * LSEQ);
    float* attng = attn + (size_t)bh * LSEQ * LSEQ;

    for (int i = t; i < 64 * 16; i += 128) {
        int d = i >> 4, s = i & 15;
        *((float4*)(smQ + d * 64 + 4 * s)) =
            *((const float4*)(QT + (size_t)d * LSEQ + q0 + 4 * s));
    }

    float zrun[8];
#pragma unroll
    for (int i = 0; i < 8; i++) zrun[i] = 0.f;

    const int ktmax = q0 >> 7;
    const int sE = 2 * (tk - tq) + 14;

    for (int kt = 0; kt <= ktmax; kt++) {
        const int k0 = kt * 128;
        __syncthreads();
        for (int i = t; i < 2048; i += 128) {       // K tile
            int d = i >> 5, s = i & 31;
            *((float4*)(smK + d * 128 + 4 * swz(s))) =
                *((const float4*)(KT + (size_t)d * LSEQ + k0 + 4 * s));
        }
        const int ebase = 1984 + k0 - q0;           // >= 0 always
        for (int i = t; i < 3072; i += 128) {       // Er band tile
            int d = i / 48, s = i - d * 48;
            int e = ebase + 4 * s;
            const float* er = ET + (size_t)d * LSEQ;
            float4 v;
            if (e + 3 < LSEQ) v = *((const float4*)(er + e));
            else {
                v.x = (e + 0 < LSEQ) ? er[e + 0] : 0.f;
                v.y = (e + 1 < LSEQ) ? er[e + 1] : 0.f;
                v.z = (e + 2 < LSEQ) ? er[e + 2] : 0.f;
                v.w = (e + 3 < LSEQ) ? er[e + 3] : 0.f;
            }
            *((float4*)(smE + d * 192 + 4 * swz(s))) = v;
        }
        __syncthreads();

        ull acc[8][4];
#pragma unroll
        for (int i = 0; i < 8; i++)
#pragma unroll
            for (int jp = 0; jp < 4; jp++) acc[i][jp] = 0ull;

#pragma unroll 4
        for (int d = 0; d < 64; d++) {
            const float* qd = smQ + d * 64;
            const float* kd = smK + d * 128;
            const float* ed = smE + d * 192;
            float4 qa = *((const float4*)(qd + 8 * tq));
            float4 qb = *((const float4*)(qd + 8 * tq + 4));
            float4 ka = *((const float4*)(kd + 4 * swz(2 * tk)));
            float4 kb = *((const float4*)(kd + 4 * swz(2 * tk + 1)));
            float4 e0 = *((const float4*)(ed + 4 * swz(sE + 0)));
            float4 e1 = *((const float4*)(ed + 4 * swz(sE + 1)));
            float4 e2 = *((const float4*)(ed + 4 * swz(sE + 2)));
            float4 e3 = *((const float4*)(ed + 4 * swz(sE + 3)));
            float w[16] = {e0.x, e0.y, e0.z, e0.w, e1.x, e1.y, e1.z, e1.w,
                           e2.x, e2.y, e2.z, e2.w, e3.x, e3.y, e3.z, e3.w};
            ull kp[4] = {pk2(ka.x, ka.y), pk2(ka.z, ka.w),
                         pk2(kb.x, kb.y), pk2(kb.z, kb.w)};
            ull ep[14];
#pragma unroll
            for (int x = 0; x < 14; x++) ep[x] = pk2(w[x], w[x + 1]);
            float qv[8] = {qa.x, qa.y, qa.z, qa.w, qb.x, qb.y, qb.z, qb.w};
#pragma unroll
            for (int i = 0; i < 8; i++) {
                ull qq = pk2(qv[i], qv[i]);
#pragma unroll
                for (int jp = 0; jp < 4; jp++) {
                    fma2(acc[i][jp], qq, kp[jp]);
                    fma2(acc[i][jp], qq, ep[7 - i + 2 * jp]);
                }
            }
        }

        const bool diag = (kt == ktmax);
        const int kg0 = k0 + 8 * tk;
#pragma unroll
        for (int i = 0; i < 8; i++) {
            const int q = q0 + 8 * tq + i;
            float p[8];
#pragma unroll
            for (int jp = 0; jp < 4; jp++) {
                float lo, hi; up2(acc[i][jp], lo, hi);
                p[2 * jp]     = __expf(lo * 0.125f);
                p[2 * jp + 1] = __expf(hi * 0.125f);
            }
            if (diag) {
#pragma unroll
                for (int j = 0; j < 8; j++) if (kg0 + j > q) p[j] = 0.f;
            }
            zrun[i] += ((p[0] + p[1]) + (p[2] + p[3])) + ((p[4] + p[5]) + (p[6] + p[7]));
            float* dst = attng + (size_t)q * LSEQ + kg0;
            *((float4*)dst)       = make_float4(p[0], p[1], p[2], p[3]);
            *((float4*)(dst + 4)) = make_float4(p[4], p[5], p[6], p[7]);
        }
    }

#pragma unroll
    for (int i = 0; i < 8; i++) {
#pragma unroll
        for (int off = 8; off >= 1; off >>= 1)
            zrun[i] += __shfl_xor_sync(0xffffffffu, zrun[i], off);
    }
    if (tk == 0) {
#pragma unroll
        for (int i = 0; i < 8; i++)
            g_IZ[bh * LSEQ + q0 + 8 * tq + i] = 1.f / zrun[i];
    }
}

// ============ Kernel B: normalize attn in place + ctx = P·V + zero-fill ====
__global__ void __launch_bounds__(128, 3)
pv_kernel(const float* __restrict__ V, float* __restrict__ ctx,
          float* __restrict__ attn)
{
    extern __shared__ float sm[];
    float* smP  = sm;                // [64][128]
    float* smV  = sm + 8192;         // [128][64]
    float* smIZ = sm + 16384;        // [64]

    if (ctx == nullptr) ctx = g_ctx_scratch;
    const int qt = 31 - (int)blockIdx.x;
    const int bh = blockIdx.y;
    const int q0 = qt * 64;
    const int t  = threadIdx.x;
    const int tq = t >> 4;           // 0..7 (8 q rows)
    const int td = t & 15;           // 0..15 (4 d cols)

    const float* Vg = V + (size_t)bh * LSEQ * D;
    float* attng = attn + (size_t)bh * LSEQ * LSEQ;
    float* ctxg  = ctx  + (size_t)bh * LSEQ * D;

    if (t < 64) smIZ[t] = g_IZ[bh * LSEQ + q0 + t];

    ull cacc[8][2];
#pragma unroll
    for (int i = 0; i < 8; i++) { cacc[i][0] = 0ull; cacc[i][1] = 0ull; }

    const int ktmax = q0 >> 7;
    for (int kt = 0; kt <= ktmax; kt++) {
        const int k0 = kt * 128;
        __syncthreads();
        for (int i = t; i < 2048; i += 128) {       // V tile [k][d]
            int k = i >> 4, s = i & 15;
            *((float4*)(smV + k * 64 + 4 * s)) =
                *((const float4*)(Vg + (size_t)(k0 + k) * D + 4 * s));
        }
        for (int i = t; i < 2048; i += 128) {       // P tile: read, scale, wb
            int r = i >> 5, c = i & 31;
            size_t gi = (size_t)(q0 + r) * LSEQ + k0 + 4 * c;
            float4 pv = *((const float4*)(attng + gi));
            float iz = smIZ[r];
            pv.x *= iz; pv.y *= iz; pv.z *= iz; pv.w *= iz;
            *((float4*)(attng + gi)) = pv;
            *((float4*)(smP + r * 128 + 4 * c)) = pv;
        }
        __syncthreads();

#pragma unroll 4
        for (int kk = 0; kk < 32; kk++) {           // 4 k per iter
            ull vp[4][2];
#pragma unroll
            for (int x = 0; x < 4; x++) {
                float4 vf = *((const float4*)(smV + (4 * kk + x) * 64 + 4 * td));
                vp[x][0] = pk2(vf.x, vf.y);
                vp[x][1] = pk2(vf.z, vf.w);
            }
#pragma unroll
            for (int i = 0; i < 8; i++) {
                float4 pf = *((const float4*)(smP + (8 * tq + i) * 128 + 4 * kk));
                float pv4[4] = {pf.x, pf.y, pf.z, pf.w};
#pragma unroll
                for (int x = 0; x < 4; x++) {
                    ull pb = pk2(pv4[x], pv4[x]);
                    fma2(cacc[i][0], pb, vp[x][0]);
                    fma2(cacc[i][1], pb, vp[x][1]);
                }
            }
        }
    }

    // zero-fill the future columns of this q-slab
    const int kend = (ktmax + 1) * 128;
    const int nz = (LSEQ - kend) >> 2;
    if (nz > 0) {
        const float4 z4 = make_float4(0.f, 0.f, 0.f, 0.f);
        for (int i = t; i < 64 * nz; i += 128) {
            int r = i / nz, c = i - r * nz;
            *((float4*)(attng + (size_t)(q0 + r) * LSEQ + kend + 4 * c)) = z4;
        }
    }

    // write context (already normalized since P was normalized)
#pragma unroll
    for (int i = 0; i < 8; i++) {
        const int q = q0 + 8 * tq + i;
        float a, b, c2, d2;
        up2(cacc[i][0], a, b); up2(cacc[i][1], c2, d2);
        *((float4*)(ctxg + (size_t)q * D + 4 * td)) = make_float4(a, b, c2, d2);
    }
}

extern "C" void kernel_launch(void* const* d_in, const int* in_sizes, int n_in,
                              void* d_out, int out_size) {
    const float* Q  = (const float*)d_in[0];
    const float* K  = (const float*)d_in[1];
    const float* V  = (const float*)d_in[2];
    const float* Er = (const float*)d_in[4];

    const long long CTXN = (long long)2 * 16 * 2048 * 64;
    const long long ATTN = (long long)2 * 16 * 2048 * 2048;

    float* out = (float*)d_out;
    float* ctx; float* attn;
    if ((long long)out_size >= CTXN + ATTN) { ctx = out; attn = out + CTXN; }
    else if ((long long)out_size == ATTN)   { ctx = nullptr; attn = out; }
    else                                    { ctx = out; attn = out; }

    transpose_kernel<<<dim3(65, 16), 256>>>(Q, K, Er);

    const int smA = (4096 + 8192 + 12288) * (int)sizeof(float);   // 96 KB
    cudaFuncSetAttribute(score_kernel,
                         cudaFuncAttributeMaxDynamicSharedMemorySize, smA);
    score_kernel<<<dim3(32, 32), 128, smA>>>(attn);

    const int smB = (8192 + 8192 + 64) * (int)sizeof(float);      // ~64 KB
    cudaFuncSetAttribute(pv_kernel,
                         cudaFuncAttributeMaxDynamicSharedMemorySize, smB);
    pv_kernel<<<dim3(32, 32), 128, smB>>>(V, ctx, attn);
}